// round 12
// baseline (speedup 1.0000x reference)
#include <cuda_runtime.h>
#include <stdint.h>

#define NN 100000
#define EE 1600000
#define F  64

// Scratch (allocation-free rule: __device__ globals).
// g_hs4 declared float4[] to GUARANTEE 16B alignment for LDG.128/RED.128.
__device__ float  g_deg[NN];
__device__ float  g_dinv[NN];
__device__ float4 g_hs4[(size_t)NN * F / 4];
__device__ int    g_stride;   // 1 if edge_index delivered as int32, 2 if int64

// ---------------------------------------------------------------------------
// K0: detect index dtype. int64 (values < 2^31) -> all odd 32-bit words zero.
// Samples lie within the int32-footprint (first 8KB), safe for both layouts.
// Deterministic: depends only on input bytes.
// ---------------------------------------------------------------------------
__global__ void k_detect(const int* __restrict__ ei32) {
    __shared__ int any;
    if (threadIdx.x == 0) any = 0;
    __syncthreads();
    int acc = 0;
    for (int j = threadIdx.x; j < 1024; j += 256)
        acc |= ei32[2 * j + 1];
    if (acc) atomicOr(&any, 1);
    __syncthreads();
    if (threadIdx.x == 0) g_stride = any ? 1 : 2;  // int32 : int64
}

// ---------------------------------------------------------------------------
// K1: deg[n] = 2.0 (improved self-loop weight)
// ---------------------------------------------------------------------------
__global__ void k_init_deg() {
    int n = blockIdx.x * blockDim.x + threadIdx.x;
    if (n < NN) g_deg[n] = 2.0f;
}

// ---------------------------------------------------------------------------
// K2: deg[dst] += edge_attr  (spread L2 atomics; deg = 400KB -> L2 resident)
// ---------------------------------------------------------------------------
__global__ void k_deg_scatter(const int* __restrict__ ei32,
                              const float* __restrict__ ea) {
    int e = blockIdx.x * blockDim.x + threadIdx.x;
    if (e < EE) {
        size_t st = (size_t)g_stride;
        int dst = ei32[((size_t)EE + e) * st];
        dst = min(max(dst, 0), NN - 1);   // defensive clamp
        atomicAdd(&g_deg[dst], ea[e]);
    }
}

// ---------------------------------------------------------------------------
// K3: h = x @ W; dinv = rsqrt(deg); hs = h * dinv (store);
//     out = b + hs * (2*dinv)   <- self-loop term + bias + out init
// 1024 threads = 16 nodes x 64 cols. W cached in shared (16KB).
// ---------------------------------------------------------------------------
__global__ __launch_bounds__(1024, 2)
void k_gemm_hs(const float* __restrict__ x, const float* __restrict__ W,
               const float* __restrict__ b, float* __restrict__ out) {
    __shared__ float Ws[F * F];
    __shared__ float xs[16 * F];
    int tid = threadIdx.x;

    #pragma unroll
    for (int i = 0; i < 4; i++)
        Ws[tid + i * 1024] = W[tid + i * 1024];

    int ln   = tid >> 6;     // local node 0..15
    int col  = tid & 63;     // output column
    int node = blockIdx.x * 16 + ln;

    xs[tid] = x[(size_t)blockIdx.x * (16 * F) + tid];   // coalesced
    __syncthreads();

    float acc = 0.0f;
    #pragma unroll
    for (int k = 0; k < F; k++)
        acc = fmaf(xs[ln * F + k], Ws[k * F + col], acc);

    float deg = g_deg[node];
    float dv  = (deg > 0.0f) ? rsqrtf(deg) : 0.0f;  // deg >= 2 always here
    if (col == 0) g_dinv[node] = dv;

    float hs = acc * dv;
    ((float*)g_hs4)[(size_t)node * F + col] = hs;
    out[(size_t)node * F + col] = b[col] + hs * (2.0f * dv);
}

// ---------------------------------------------------------------------------
// K4: per edge e: out[dst] += hs[src] * (edge_attr[e] * dinv[dst])
// 8 threads per edge, TWO float4 each (offsets q and q+8) -> MLP=2.
// Vector atomicAdd(float4*) lowers to RED.E.ADD.F32.V4 (no return).
// Leader lane per 8-lane segment loads indices + computes coeff; shfl bcast.
// hs (25.6MB) + out (25.6MB) L2-resident -> L2-bandwidth-bound kernel.
// ---------------------------------------------------------------------------
__global__ __launch_bounds__(256)
void k_edge_scatter(const int* __restrict__ ei32,
                    const float* __restrict__ ea,
                    float* __restrict__ out) {
    long long t = (long long)blockIdx.x * blockDim.x + threadIdx.x;
    int e = (int)(t >> 3);
    int q = (int)(t & 7);
    if (e >= EE) return;

    int src_l = 0, dst_l = 0;
    float coeff_l = 0.0f;
    if (q == 0) {
        size_t st = (size_t)g_stride;
        src_l = ei32[(size_t)e * st];
        dst_l = ei32[((size_t)EE + e) * st];
        src_l = min(max(src_l, 0), NN - 1);   // defensive clamp
        dst_l = min(max(dst_l, 0), NN - 1);
        coeff_l = ea[e] * g_dinv[dst_l];
    }
    // broadcast from lane 0 of each 8-lane segment
    int   src   = __shfl_sync(0xffffffffu, src_l,   0, 8);
    int   dst   = __shfl_sync(0xffffffffu, dst_l,   0, 8);
    float coeff = __shfl_sync(0xffffffffu, coeff_l, 0, 8);

    const float4* hp = g_hs4 + (size_t)src * (F / 4);
    float4 v0 = hp[q];          // independent loads -> MLP=2
    float4 v1 = hp[q + 8];

    float4* op = (float4*)(out + (size_t)dst * F);
    float4 m0 = make_float4(v0.x * coeff, v0.y * coeff, v0.z * coeff, v0.w * coeff);
    float4 m1 = make_float4(v1.x * coeff, v1.y * coeff, v1.z * coeff, v1.w * coeff);
    atomicAdd(op + q,     m0);   // sm_90+ vector reduction (RED.128)
    atomicAdd(op + q + 8, m1);
}

// ---------------------------------------------------------------------------
// Inputs resolved BY ELEMENT COUNT (all six distinct), immune to metadata
// ordering: x=NN*F, ea=EE, W=F*F, b=F, ei=2*EE, batch=NN. Output [NN,F] f32.
// Index dtype (int32 vs int64) resolved at runtime by k_detect.
// ---------------------------------------------------------------------------
extern "C" void kernel_launch(void* const* d_in, const int* in_sizes, int n_in,
                              void* d_out, int out_size) {
    const float* x  = nullptr;
    const float* ea = nullptr;
    const float* W  = nullptr;
    const float* b  = nullptr;
    const int*   ei = nullptr;

    for (int i = 0; i < n_in; i++) {
        switch (in_sizes[i]) {
            case NN * F:  x  = (const float*)d_in[i]; break;  // 6,400,000
            case EE:      ea = (const float*)d_in[i]; break;  // 1,600,000
            case F * F:   W  = (const float*)d_in[i]; break;  // 4,096
            case F:       b  = (const float*)d_in[i]; break;  // 64
            case 2 * EE:  ei = (const int*)d_in[i];   break;  // 3,200,000
            default: break;                                    // batch (NN)
        }
    }

    float* out = (float*)d_out;

    k_detect<<<1, 256>>>(ei);
    k_init_deg<<<(NN + 255) / 256, 256>>>();
    k_deg_scatter<<<(EE + 255) / 256, 256>>>(ei, ea);
    k_gemm_hs<<<NN / 16, 1024>>>(x, W, b, out);

    long long total = (long long)EE * 8;
    int blocks = (int)((total + 255) / 256);
    k_edge_scatter<<<blocks, 256>>>(ei, ea, out);
}

// round 15
// speedup vs baseline: 1.4590x; 1.4590x over previous
#include <cuda_runtime.h>
#include <stdint.h>

#define NN 100000
#define EE 1600000
#define F  64
#define TN 32          // nodes per K3 block (100000/32 = 3125 exact)

// Scratch (allocation-free rule: __device__ globals).
__device__ float  g_deg[NN];
__device__ float  g_dinv[NN];
__device__ float4 g_hs4[(size_t)NN * F / 4];
__device__ int    g_stride;   // 1 if edge_index delivered as int32, 2 if int64

// ---------------------------------------------------------------------------
// K0: detect index dtype. int64 (values < 2^31) -> all odd 32-bit words zero.
// ---------------------------------------------------------------------------
__global__ void k_detect(const int* __restrict__ ei32) {
    __shared__ int any;
    if (threadIdx.x == 0) any = 0;
    __syncthreads();
    int acc = 0;
    for (int j = threadIdx.x; j < 1024; j += 256)
        acc |= ei32[2 * j + 1];
    if (acc) atomicOr(&any, 1);
    __syncthreads();
    if (threadIdx.x == 0) g_stride = any ? 1 : 2;  // int32 : int64
}

// ---------------------------------------------------------------------------
// K1: deg[n] = 2.0 (improved self-loop weight)
// ---------------------------------------------------------------------------
__global__ void k_init_deg() {
    int n = blockIdx.x * blockDim.x + threadIdx.x;
    if (n < NN) g_deg[n] = 2.0f;
}

// ---------------------------------------------------------------------------
// K2: deg[dst] += edge_attr  (spread L2 atomics; deg = 400KB -> L2 resident)
// ---------------------------------------------------------------------------
__global__ void k_deg_scatter(const int* __restrict__ ei32,
                              const float* __restrict__ ea) {
    int e = blockIdx.x * blockDim.x + threadIdx.x;
    if (e < EE) {
        size_t st = (size_t)g_stride;
        int dst = ei32[((size_t)EE + e) * st];
        dst = min(max(dst, 0), NN - 1);
        atomicAdd(&g_deg[dst], ea[e]);
    }
}

// ---------------------------------------------------------------------------
// K3 v2: register-tiled GEMM. 128 threads, 32-node tile.
// Thread (cg, ng): cols 4cg..4cg+3 of nodes 4ng..4ng+3 (4x4 = 16 outputs).
// Per 4-k step: 4 LDS.128 of W + 4 LDS.128 of x for 64 FMA -> 2 B/FMA
// (was 8 B/FMA scalar => measured 86.8us L1-bound; 4x LDS reduction).
// Epilogue: dinv = rsqrt(deg); hs = h*dinv stored; out = b + hs*2*dinv.
// ---------------------------------------------------------------------------
__global__ __launch_bounds__(128)
void k_gemm_hs(const float* __restrict__ x, const float* __restrict__ W,
               const float* __restrict__ b, float* __restrict__ out) {
    __shared__ float4 Ws4[F * F / 4];      // [k][cg]   : 1024 float4 = 16KB
    __shared__ float4 xs4[TN * F / 4];     // [node][k4]:  512 float4 =  8KB

    int tid = threadIdx.x;
    int cg  = tid & 15;    // column group (4 cols)
    int ng  = tid >> 4;    // node group   (4 nodes), 8 groups
    int base = blockIdx.x * TN;

    #pragma unroll
    for (int i = 0; i < 8; i++)
        Ws4[tid + i * 128] = ((const float4*)W)[tid + i * 128];
    #pragma unroll
    for (int i = 0; i < 4; i++)
        xs4[tid + i * 128] = ((const float4*)x)[(size_t)base * (F / 4) + tid + i * 128];
    __syncthreads();

    float4 acc[4];
    #pragma unroll
    for (int n = 0; n < 4; n++) acc[n] = make_float4(0.f, 0.f, 0.f, 0.f);

    #pragma unroll
    for (int k4 = 0; k4 < F / 4; k4++) {
        float4 w0 = Ws4[(4 * k4 + 0) * 16 + cg];
        float4 w1 = Ws4[(4 * k4 + 1) * 16 + cg];
        float4 w2 = Ws4[(4 * k4 + 2) * 16 + cg];
        float4 w3 = Ws4[(4 * k4 + 3) * 16 + cg];
        #pragma unroll
        for (int n = 0; n < 4; n++) {
            float4 xv = xs4[(ng * 4 + n) * 16 + k4];
            acc[n].x = fmaf(xv.x, w0.x, fmaf(xv.y, w1.x, fmaf(xv.z, w2.x, fmaf(xv.w, w3.x, acc[n].x))));
            acc[n].y = fmaf(xv.x, w0.y, fmaf(xv.y, w1.y, fmaf(xv.z, w2.y, fmaf(xv.w, w3.y, acc[n].y))));
            acc[n].z = fmaf(xv.x, w0.z, fmaf(xv.y, w1.z, fmaf(xv.z, w2.z, fmaf(xv.w, w3.z, acc[n].z))));
            acc[n].w = fmaf(xv.x, w0.w, fmaf(xv.y, w1.w, fmaf(xv.z, w2.w, fmaf(xv.w, w3.w, acc[n].w))));
        }
    }

    float4 bv = ((const float4*)b)[cg];

    #pragma unroll
    for (int n = 0; n < 4; n++) {
        int node = base + ng * 4 + n;
        float deg = g_deg[node];
        float dv  = (deg > 0.0f) ? rsqrtf(deg) : 0.0f;
        if (cg == 0) g_dinv[node] = dv;

        float4 hs = make_float4(acc[n].x * dv, acc[n].y * dv,
                                acc[n].z * dv, acc[n].w * dv);
        g_hs4[(size_t)node * 16 + cg] = hs;

        float dv2 = 2.0f * dv;
        float4 o = make_float4(bv.x + hs.x * dv2, bv.y + hs.y * dv2,
                               bv.z + hs.z * dv2, bv.w + hs.w * dv2);
        ((float4*)out)[(size_t)node * 16 + cg] = o;
    }
}

// ---------------------------------------------------------------------------
// K4: per edge e: out[dst] += hs[src] * (edge_attr[e] * dinv[dst])
// 8 threads per edge, TWO float4 each -> MLP=2; RED.E.ADD.F32.V4 scatter.
// ---------------------------------------------------------------------------
__global__ __launch_bounds__(256)
void k_edge_scatter(const int* __restrict__ ei32,
                    const float* __restrict__ ea,
                    float* __restrict__ out) {
    long long t = (long long)blockIdx.x * blockDim.x + threadIdx.x;
    int e = (int)(t >> 3);
    int q = (int)(t & 7);
    if (e >= EE) return;

    int src_l = 0, dst_l = 0;
    float coeff_l = 0.0f;
    if (q == 0) {
        size_t st = (size_t)g_stride;
        src_l = ei32[(size_t)e * st];
        dst_l = ei32[((size_t)EE + e) * st];
        src_l = min(max(src_l, 0), NN - 1);
        dst_l = min(max(dst_l, 0), NN - 1);
        coeff_l = ea[e] * g_dinv[dst_l];
    }
    int   src   = __shfl_sync(0xffffffffu, src_l,   0, 8);
    int   dst   = __shfl_sync(0xffffffffu, dst_l,   0, 8);
    float coeff = __shfl_sync(0xffffffffu, coeff_l, 0, 8);

    const float4* hp = g_hs4 + (size_t)src * (F / 4);
    float4 v0 = hp[q];
    float4 v1 = hp[q + 8];

    float4* op = (float4*)(out + (size_t)dst * F);
    float4 m0 = make_float4(v0.x * coeff, v0.y * coeff, v0.z * coeff, v0.w * coeff);
    float4 m1 = make_float4(v1.x * coeff, v1.y * coeff, v1.z * coeff, v1.w * coeff);
    atomicAdd(op + q,     m0);
    atomicAdd(op + q + 8, m1);
}

// ---------------------------------------------------------------------------
// Inputs resolved BY ELEMENT COUNT (all six distinct), immune to metadata
// ordering. Index dtype (int32 vs int64) resolved at runtime by k_detect.
// ---------------------------------------------------------------------------
extern "C" void kernel_launch(void* const* d_in, const int* in_sizes, int n_in,
                              void* d_out, int out_size) {
    const float* x  = nullptr;
    const float* ea = nullptr;
    const float* W  = nullptr;
    const float* b  = nullptr;
    const int*   ei = nullptr;

    for (int i = 0; i < n_in; i++) {
        switch (in_sizes[i]) {
            case NN * F:  x  = (const float*)d_in[i]; break;
            case EE:      ea = (const float*)d_in[i]; break;
            case F * F:   W  = (const float*)d_in[i]; break;
            case F:       b  = (const float*)d_in[i]; break;
            case 2 * EE:  ei = (const int*)d_in[i];   break;
            default: break;   // batch (NN)
        }
    }

    float* out = (float*)d_out;

    k_detect<<<1, 256>>>(ei);
    k_init_deg<<<(NN + 255) / 256, 256>>>();
    k_deg_scatter<<<(EE + 255) / 256, 256>>>(ei, ea);
    k_gemm_hs<<<NN / TN, 128>>>(x, W, b, out);

    long long total = (long long)EE * 8;
    int blocks = (int)((total + 255) / 256);
    k_edge_scatter<<<blocks, 256>>>(ei, ea, out);
}

// round 16
// speedup vs baseline: 1.5332x; 1.0509x over previous
#include <cuda_runtime.h>
#include <stdint.h>

#define NN 100000
#define EE 1600000
#define F  64
#define TN 64          // nodes per K3 block; grid = ceil(100000/64) = 1563

// Scratch (allocation-free rule: __device__ globals).
__device__ float  g_deg[NN];
__device__ float  g_dinv[NN];
__device__ float4 g_hs4[(size_t)NN * F / 4];
__device__ int    g_stride;   // 1 if edge_index delivered as int32, 2 if int64

// ---------------------------------------------------------------------------
// K01: fused init + dtype detect. Blocks 0..390 set deg=2.0 (self-loop w);
// block 391 detects index dtype (int64 -> odd 32-bit words all zero; samples
// lie in first 8KB, within the int32 footprint, safe for both layouts).
// ---------------------------------------------------------------------------
__global__ void k_prep(const int* __restrict__ ei32) {
    if (blockIdx.x < 391) {
        int n = blockIdx.x * 256 + threadIdx.x;
        if (n < NN) g_deg[n] = 2.0f;
    } else {
        __shared__ int any;
        if (threadIdx.x == 0) any = 0;
        __syncthreads();
        int acc = 0;
        for (int j = threadIdx.x; j < 1024; j += 256)
            acc |= ei32[2 * j + 1];
        if (acc) atomicOr(&any, 1);
        __syncthreads();
        if (threadIdx.x == 0) g_stride = any ? 1 : 2;  // int32 : int64
    }
}

// ---------------------------------------------------------------------------
// K2: deg[dst] += edge_attr  (spread L2 atomics; deg = 400KB -> L2 resident)
// ---------------------------------------------------------------------------
__global__ void k_deg_scatter(const int* __restrict__ ei32,
                              const float* __restrict__ ea) {
    int e = blockIdx.x * blockDim.x + threadIdx.x;
    if (e < EE) {
        size_t st = (size_t)g_stride;
        int dst = ei32[((size_t)EE + e) * st];
        dst = min(max(dst, 0), NN - 1);
        atomicAdd(&g_deg[dst], ea[e]);
    }
}

// ---------------------------------------------------------------------------
// K3 v3: register-tiled GEMM. 128 threads, 64-node tile.
// Thread (cg, ng): cols 4cg..4cg+3 of nodes 8ng..8ng+7 (8x4 = 32 outputs).
// Per 4-k step: 4 LDS.128 of W + 8 LDS.128 of x for 128 FMA -> 1.5 B/FMA
// (v2 was 2 B/FMA, measured 28.7us @ L1=78.2%; this cuts LDS bytes 25%).
// x loads are per-phase broadcasts; W loads 128B-contiguous per phase:
// both conflict-free. Epilogue: dinv=rsqrt(deg); hs=h*dinv; out=b+hs*2*dinv.
// ---------------------------------------------------------------------------
__global__ __launch_bounds__(128)
void k_gemm_hs(const float* __restrict__ x, const float* __restrict__ W,
               const float* __restrict__ b, float* __restrict__ out) {
    __shared__ float4 Ws4[F * F / 4];      // [k][cg]   : 1024 float4 = 16KB
    __shared__ float4 xs4[TN * F / 4];     // [node][k4]: 1024 float4 = 16KB

    int tid = threadIdx.x;
    int cg  = tid & 15;    // column group (4 cols)
    int ng  = tid >> 4;    // node group   (8 nodes), 8 groups
    int base = blockIdx.x * TN;
    int nvalid = min(TN, NN - base);       // 64, or 32 in the last block

    #pragma unroll
    for (int i = 0; i < 8; i++)
        Ws4[tid + i * 128] = ((const float4*)W)[tid + i * 128];
    for (int i = tid; i < nvalid * 16; i += 128)
        xs4[i] = ((const float4*)x)[(size_t)base * 16 + i];
    __syncthreads();

    float4 acc[8];
    #pragma unroll
    for (int n = 0; n < 8; n++) acc[n] = make_float4(0.f, 0.f, 0.f, 0.f);

    #pragma unroll
    for (int k4 = 0; k4 < F / 4; k4++) {
        float4 w0 = Ws4[(4 * k4 + 0) * 16 + cg];
        float4 w1 = Ws4[(4 * k4 + 1) * 16 + cg];
        float4 w2 = Ws4[(4 * k4 + 2) * 16 + cg];
        float4 w3 = Ws4[(4 * k4 + 3) * 16 + cg];
        #pragma unroll
        for (int n = 0; n < 8; n++) {
            float4 xv = xs4[(ng * 8 + n) * 16 + k4];
            acc[n].x = fmaf(xv.x, w0.x, fmaf(xv.y, w1.x, fmaf(xv.z, w2.x, fmaf(xv.w, w3.x, acc[n].x))));
            acc[n].y = fmaf(xv.x, w0.y, fmaf(xv.y, w1.y, fmaf(xv.z, w2.y, fmaf(xv.w, w3.y, acc[n].y))));
            acc[n].z = fmaf(xv.x, w0.z, fmaf(xv.y, w1.z, fmaf(xv.z, w2.z, fmaf(xv.w, w3.z, acc[n].z))));
            acc[n].w = fmaf(xv.x, w0.w, fmaf(xv.y, w1.w, fmaf(xv.z, w2.w, fmaf(xv.w, w3.w, acc[n].w))));
        }
    }

    float4 bv = ((const float4*)b)[cg];

    #pragma unroll
    for (int n = 0; n < 8; n++) {
        int node = base + ng * 8 + n;
        if (node < NN) {
            float deg = g_deg[node];
            float dv  = (deg > 0.0f) ? rsqrtf(deg) : 0.0f;
            if (cg == 0) g_dinv[node] = dv;

            float4 hs = make_float4(acc[n].x * dv, acc[n].y * dv,
                                    acc[n].z * dv, acc[n].w * dv);
            g_hs4[(size_t)node * 16 + cg] = hs;

            float dv2 = 2.0f * dv;
            float4 o = make_float4(bv.x + hs.x * dv2, bv.y + hs.y * dv2,
                                   bv.z + hs.z * dv2, bv.w + hs.w * dv2);
            ((float4*)out)[(size_t)node * 16 + cg] = o;
        }
    }
}

// ---------------------------------------------------------------------------
// K4: per edge e: out[dst] += hs[src] * (edge_attr[e] * dinv[dst])
// 8 threads per edge, TWO float4 each -> MLP=2; RED.E.ADD.F32.V4 scatter.
// ---------------------------------------------------------------------------
__global__ __launch_bounds__(256)
void k_edge_scatter(const int* __restrict__ ei32,
                    const float* __restrict__ ea,
                    float* __restrict__ out) {
    long long t = (long long)blockIdx.x * blockDim.x + threadIdx.x;
    int e = (int)(t >> 3);
    int q = (int)(t & 7);
    if (e >= EE) return;

    int src_l = 0, dst_l = 0;
    float coeff_l = 0.0f;
    if (q == 0) {
        size_t st = (size_t)g_stride;
        src_l = ei32[(size_t)e * st];
        dst_l = ei32[((size_t)EE + e) * st];
        src_l = min(max(src_l, 0), NN - 1);
        dst_l = min(max(dst_l, 0), NN - 1);
        coeff_l = ea[e] * g_dinv[dst_l];
    }
    int   src   = __shfl_sync(0xffffffffu, src_l,   0, 8);
    int   dst   = __shfl_sync(0xffffffffu, dst_l,   0, 8);
    float coeff = __shfl_sync(0xffffffffu, coeff_l, 0, 8);

    const float4* hp = g_hs4 + (size_t)src * (F / 4);
    float4 v0 = hp[q];
    float4 v1 = hp[q + 8];

    float4* op = (float4*)(out + (size_t)dst * F);
    float4 m0 = make_float4(v0.x * coeff, v0.y * coeff, v0.z * coeff, v0.w * coeff);
    float4 m1 = make_float4(v1.x * coeff, v1.y * coeff, v1.z * coeff, v1.w * coeff);
    atomicAdd(op + q,     m0);
    atomicAdd(op + q + 8, m1);
}

// ---------------------------------------------------------------------------
// Inputs resolved BY ELEMENT COUNT (all six distinct), immune to metadata
// ordering. Index dtype (int32 vs int64) resolved at runtime in k_prep.
// ---------------------------------------------------------------------------
extern "C" void kernel_launch(void* const* d_in, const int* in_sizes, int n_in,
                              void* d_out, int out_size) {
    const float* x  = nullptr;
    const float* ea = nullptr;
    const float* W  = nullptr;
    const float* b  = nullptr;
    const int*   ei = nullptr;

    for (int i = 0; i < n_in; i++) {
        switch (in_sizes[i]) {
            case NN * F:  x  = (const float*)d_in[i]; break;
            case EE:      ea = (const float*)d_in[i]; break;
            case F * F:   W  = (const float*)d_in[i]; break;
            case F:       b  = (const float*)d_in[i]; break;
            case 2 * EE:  ei = (const int*)d_in[i];   break;
            default: break;   // batch (NN)
        }
    }

    float* out = (float*)d_out;

    k_prep<<<392, 256>>>(ei);                       // init deg + dtype detect
    k_deg_scatter<<<(EE + 255) / 256, 256>>>(ei, ea);
    k_gemm_hs<<<(NN + TN - 1) / TN, 128>>>(x, W, b, out);

    long long total = (long long)EE * 8;
    int blocks = (int)((total + 255) / 256);
    k_edge_scatter<<<blocks, 256>>>(ei, ea, out);
}